// round 15
// baseline (speedup 1.0000x reference)
#include <cuda_runtime.h>
#include <cuda_bf16.h>
#include <cstdint>

#define N_NODES 50000
#define N_EDGES 320000
#define GSCAN   ((N_NODES + 1023) / 1024)

// ---------------- static scratch (no allocations allowed) ----------------
__device__ float g_A[(size_t)N_NODES * 1024];   // activation buffer A (tf32-rounded fp32)
__device__ float g_B[(size_t)N_NODES * 2048];   // activation buffer B (tf32-rounded fp32)
__device__ float g_tmp[(size_t)N_NODES * 1024]; // GEMM fp32 out (pre-agg), max d=1024
__device__ float g_W[4 * 1024 * 1024];          // transposed weights (tf32-rounded fp32)

__device__ int   g_deg[N_NODES];
__device__ float g_dinv[N_NODES];
__device__ int   g_rowptr[N_NODES + 1];
__device__ int   g_fill[N_NODES];
__device__ int   g_csr[N_EDGES];
__device__ int   g_bsum[64];
__device__ int   g_is64;

// ---------------- tf32 rounding helper ----------------
__device__ __forceinline__ float to_tf32(float v) {
    uint32_t u;
    asm("cvt.rna.tf32.f32 %0, %1;" : "=r"(u) : "f"(v));
    return __uint_as_float(u);
}

// ---------------- index dtype handling ----------------
__device__ __forceinline__ int get_idx(const void* e, long long i) {
    if (g_is64) return (int)((const long long*)e)[i];
    return ((const int*)e)[i];
}

// ---------------- graph preprocessing ----------------
// also detects index dtype (block 0, thread 0) — consumed by LATER kernels only
__global__ void zero_deg_kernel(const void* e) {
    int i = blockIdx.x * blockDim.x + threadIdx.x;
    if (i < N_NODES) g_deg[i] = 0;
    if (blockIdx.x == 0 && threadIdx.x == 0) {
        const int* w = (const int*)e;
        int all0 = 1;
        for (int j = 1; j < 64; j += 2)
            if (w[j] != 0) all0 = 0;
        g_is64 = all0;
    }
}

__global__ void count_deg_kernel(const void* e) {
    int i = blockIdx.x * blockDim.x + threadIdx.x;
    if (i >= N_EDGES) return;
    int dst = get_idx(e, (long long)N_EDGES + i);
    atomicAdd(&g_deg[dst], 1);
}

__global__ void block_sum_kernel() {
    int i = blockIdx.x * 1024 + threadIdx.x;
    int v = (i < N_NODES) ? g_deg[i] : 0;
    int lane = threadIdx.x & 31, warp = threadIdx.x >> 5;
#pragma unroll
    for (int off = 16; off > 0; off >>= 1) v += __shfl_down_sync(0xffffffffu, v, off);
    __shared__ int ws[32];
    if (lane == 0) ws[warp] = v;
    __syncthreads();
    if (warp == 0) {
        int s = ws[lane];
#pragma unroll
        for (int off = 16; off > 0; off >>= 1) s += __shfl_down_sync(0xffffffffu, s, off);
        if (lane == 0) g_bsum[blockIdx.x] = s;
    }
}

__global__ void scan_partials_kernel() {
    int acc = 0;
    for (int i = 0; i < GSCAN; i++) { int t = g_bsum[i]; g_bsum[i] = acc; acc += t; }
    g_rowptr[N_NODES] = acc;
}

__global__ void scatter_scan_kernel() {
    int i = blockIdx.x * 1024 + threadIdx.x;
    int v = (i < N_NODES) ? g_deg[i] : 0;
    int lane = threadIdx.x & 31, warp = threadIdx.x >> 5;
    int incl = v;
#pragma unroll
    for (int off = 1; off < 32; off <<= 1) {
        int t = __shfl_up_sync(0xffffffffu, incl, off);
        if (lane >= off) incl += t;
    }
    __shared__ int ws[32];
    if (lane == 31) ws[warp] = incl;
    __syncthreads();
    if (warp == 0) {
        int s = ws[lane];
#pragma unroll
        for (int off = 1; off < 32; off <<= 1) {
            int t = __shfl_up_sync(0xffffffffu, s, off);
            if (lane >= off) s += t;
        }
        ws[lane] = s;
    }
    __syncthreads();
    int wbase = (warp == 0) ? 0 : ws[warp - 1];
    int excl = g_bsum[blockIdx.x] + wbase + incl - v;
    if (i < N_NODES) {
        g_rowptr[i] = excl;
        g_fill[i]   = excl;
        g_dinv[i]   = rsqrtf((float)v + 1.0f);
    }
}

__global__ void fill_csr_kernel(const void* e) {
    int i = blockIdx.x * blockDim.x + threadIdx.x;
    if (i >= N_EDGES) return;
    int src = get_idx(e, i);
    int dst = get_idx(e, (long long)N_EDGES + i);
    int pos = atomicAdd(&g_fill[dst], 1);
    g_csr[pos] = src;
}

// ---------------- weight conversion: W [K,N] -> Wt [N,K] tf32 ----------------
__global__ void convert_w_kernel(const float* __restrict__ W, long long off, int K, int N) {
    int idx = blockIdx.x * blockDim.x + threadIdx.x;
    if (idx >= K * N) return;
    int k = idx / N, n = idx % N;
    g_W[off + (size_t)n * K + k] = to_tf32(W[idx]);
}

// ---------------- tf32 tensor-core GEMM (mma.sync.m16n8k8) ----------------
// C[M,N] = A[M,K] @ Wt[N,K]^T, operands tf32-rounded fp32.
// 128x128x32 tiles, 256 threads (8 warps of 64x32), cp.async 2-stage with
// single-barrier pipeline, 128B rows + 8-chunk xor swizzle, ldmatrix.x4.
// mode 0: store fp32 C.  mode 1: fused bias+relu+tf32-round into O.
__device__ __forceinline__ void ldm4(uint32_t* r, uint32_t addr) {
    asm volatile("ldmatrix.sync.aligned.m8n8.x4.shared.b16 {%0,%1,%2,%3}, [%4];"
                 : "=r"(r[0]), "=r"(r[1]), "=r"(r[2]), "=r"(r[3]) : "r"(addr));
}

__device__ __forceinline__ void mma_tf32(float* c, const uint32_t* a, const uint32_t* b) {
    asm volatile(
        "mma.sync.aligned.m16n8k8.row.col.f32.tf32.tf32.f32 "
        "{%0,%1,%2,%3},{%4,%5,%6,%7},{%8,%9},{%0,%1,%2,%3};"
        : "+f"(c[0]), "+f"(c[1]), "+f"(c[2]), "+f"(c[3])
        : "r"(a[0]), "r"(a[1]), "r"(a[2]), "r"(a[3]), "r"(b[0]), "r"(b[1]));
}

__device__ __forceinline__ void cp16(uint32_t dst, const void* src, bool pred) {
    int sz = pred ? 16 : 0;
    asm volatile("cp.async.cg.shared.global [%0], [%1], 16, %2;\n"
                 :: "r"(dst), "l"(src), "r"(sz));
}

// stage (32KB): A rows[0,16K): 128 x 128B; B rows[16K,32K): 128 x 128B.
// row r: 8 chunks of 16B (4 tf32); logical chunk c at physical c ^ (r & 7).
__device__ __forceinline__ void load_stage(
    uint32_t sbase, int stage,
    const float* __restrict__ A, const float* __restrict__ B,
    int bm, int bn, int k0, int M, int K, int tid)
{
    uint32_t st = sbase + stage * 32768;
#pragma unroll
    for (int h = 0; h < 4; h++) {
        int i = tid + h * 256;
        int row = i >> 3, c = i & 7;
        uint32_t doff = (uint32_t)(row * 128 + (c ^ (row & 7)) * 16);
        long arow = bm + row;
        bool av = arow < M;
        long ar = av ? arow : 0;
        cp16(st + doff, A + (size_t)ar * K + k0 + c * 4, av);
    }
#pragma unroll
    for (int h = 0; h < 4; h++) {
        int i = tid + h * 256;
        int row = i >> 3, c = i & 7;
        uint32_t doff = (uint32_t)(row * 128 + (c ^ (row & 7)) * 16);
        cp16(st + 16384 + doff, B + (size_t)(bn + row) * K + k0 + c * 4, true);
    }
    asm volatile("cp.async.commit_group;\n");
}

__global__ void __launch_bounds__(256)
bgemm_kernel(const float* __restrict__ A, const float* __restrict__ W,
             float* __restrict__ C, const float* __restrict__ bias,
             float* __restrict__ O, int M, int N, int K, int mode)
{
    extern __shared__ __align__(16) char smem[];
    uint32_t sbase = (uint32_t)__cvta_generic_to_shared(smem);

    int tid  = threadIdx.x;
    int lane = tid & 31, wid = tid >> 5;
    int wm = (wid >> 2) * 64;
    int wn = (wid & 3) * 32;
    int bm = blockIdx.y * 128;
    int bn = blockIdx.x * 128;

    float acc[4][4][4];
#pragma unroll
    for (int i = 0; i < 4; i++)
#pragma unroll
        for (int j = 0; j < 4; j++)
#pragma unroll
            for (int r = 0; r < 4; r++) acc[i][j][r] = 0.f;

    int nk = K >> 5;
    load_stage(sbase, 0, A, W, bm, bn, 0, M, K, tid);

    int lr = lane & 15, lc = lane >> 4;

    for (int kt = 0; kt < nk; kt++) {
        // single-barrier pipeline:
        //   wait: stage (kt&1) data has arrived
        //   bar : all threads finished computing kt-1 -> other stage reusable
        //   load: issue kt+1 into other stage (overlaps compute below)
        asm volatile("cp.async.wait_group 0;\n");
        __syncthreads();
        if (kt + 1 < nk)
            load_stage(sbase, (kt + 1) & 1, A, W, bm, bn, (kt + 1) * 32, M, K, tid);

        uint32_t st = sbase + (kt & 1) * 32768;
#pragma unroll
        for (int s = 0; s < 4; s++) {          // 4 k8-steps per 32-k tile
            int c = s * 2 + lc;                // logical 16B chunk
            uint32_t bf[4][2];
#pragma unroll
            for (int p = 0; p < 2; p++) {
                int row = wn + p * 16 + lr;
                uint32_t r4[4];
                ldm4(r4, st + 16384 + (uint32_t)(row * 128 + ((c ^ (row & 7)) << 4)));
                bf[2 * p][0] = r4[0];     bf[2 * p][1] = r4[2];
                bf[2 * p + 1][0] = r4[1]; bf[2 * p + 1][1] = r4[3];
            }
#pragma unroll
            for (int fm = 0; fm < 4; fm++) {
                int row = wm + fm * 16 + lr;
                uint32_t a4[4];
                ldm4(a4, st + (uint32_t)(row * 128 + ((c ^ (row & 7)) << 4)));
#pragma unroll
                for (int fn = 0; fn < 4; fn++)
                    mma_tf32(acc[fm][fn], a4, bf[fn]);
            }
        }
    }

    int g = lane >> 2, tg = lane & 3;
    if (mode == 0) {
#pragma unroll
        for (int fm = 0; fm < 4; fm++) {
#pragma unroll
            for (int fn = 0; fn < 4; fn++) {
                int row = bm + wm + fm * 16 + g;
                int col = bn + wn + fn * 8 + tg * 2;
                if (row < M)
                    *(float2*)&C[(size_t)row * N + col] = make_float2(acc[fm][fn][0], acc[fm][fn][1]);
                if (row + 8 < M)
                    *(float2*)&C[(size_t)(row + 8) * N + col] = make_float2(acc[fm][fn][2], acc[fm][fn][3]);
            }
        }
    } else {
#pragma unroll
        for (int fm = 0; fm < 4; fm++) {
#pragma unroll
            for (int fn = 0; fn < 4; fn++) {
                int col = bn + wn + fn * 8 + tg * 2;
                float2 bv = *(const float2*)&bias[col];
#pragma unroll
                for (int h = 0; h < 2; h++) {
                    int row = bm + wm + fm * 16 + g + h * 8;
                    if (row >= M) continue;
                    float v0 = to_tf32(fmaxf(acc[fm][fn][h * 2]     + bv.x, 0.f));
                    float v1 = to_tf32(fmaxf(acc[fm][fn][h * 2 + 1] + bv.y, 0.f));
                    *(float2*)&O[(size_t)row * N + col] = make_float2(v0, v1);
                }
            }
        }
    }
}

// ---------------- aggregation of raw input x (d=512) -> tf32 fp32 ----------------
__global__ void __launch_bounds__(128)
aggx_kernel(const float* __restrict__ x, float* __restrict__ o)
{
    const int d = 512;
    int node = blockIdx.x;
    int tid  = threadIdx.x;
    float di = g_dinv[node];
    int beg = g_rowptr[node];
    int end = g_rowptr[node + 1];

    float selfn = di * di;
    float4 v = ((const float4*)(x + (size_t)node * d))[tid];
    float4 acc0 = make_float4(v.x * selfn, v.y * selfn, v.z * selfn, v.w * selfn);
    float4 acc1 = make_float4(0.f, 0.f, 0.f, 0.f);

    int e = beg;
    for (; e + 1 < end; e += 2) {
        int s0 = g_csr[e], s1 = g_csr[e + 1];
        float n0 = di * g_dinv[s0], n1 = di * g_dinv[s1];
        float4 w0 = ((const float4*)(x + (size_t)s0 * d))[tid];
        float4 w1 = ((const float4*)(x + (size_t)s1 * d))[tid];
        acc0.x += w0.x * n0; acc0.y += w0.y * n0;
        acc0.z += w0.z * n0; acc0.w += w0.w * n0;
        acc1.x += w1.x * n1; acc1.y += w1.y * n1;
        acc1.z += w1.z * n1; acc1.w += w1.w * n1;
    }
    if (e < end) {
        int s0 = g_csr[e];
        float n0 = di * g_dinv[s0];
        float4 w0 = ((const float4*)(x + (size_t)s0 * d))[tid];
        acc0.x += w0.x * n0; acc0.y += w0.y * n0;
        acc0.z += w0.z * n0; acc0.w += w0.w * n0;
    }
    acc0.x += acc1.x; acc0.y += acc1.y; acc0.z += acc1.z; acc0.w += acc1.w;

    float4 r = make_float4(to_tf32(acc0.x), to_tf32(acc0.y), to_tf32(acc0.z), to_tf32(acc0.w));
    ((float4*)(o + (size_t)node * d))[tid] = r;
}

// ---------------- CSR aggregation, wide (d = 512 or 1024), block per node --------
__global__ void __launch_bounds__(128)
agg_wide_kernel(const float* __restrict__ tmp, const float* __restrict__ bias,
                float* __restrict__ o, int d)
{
    int node = blockIdx.x;
    int tid  = threadIdx.x;
    float di = g_dinv[node];
    int beg = g_rowptr[node];
    int end = g_rowptr[node + 1];
    int nc4 = d >> 2;

    float4 acc0[2], acc1[2];
    float selfn = di * di;
    const float4* selfrow = (const float4*)(tmp + (size_t)node * d);
#pragma unroll
    for (int j = 0; j < 2; j++) {
        int c = tid + j * 128;
        if (c < nc4) {
            float4 v = selfrow[c];
            acc0[j] = make_float4(v.x * selfn, v.y * selfn, v.z * selfn, v.w * selfn);
        } else acc0[j] = make_float4(0.f, 0.f, 0.f, 0.f);
        acc1[j] = make_float4(0.f, 0.f, 0.f, 0.f);
    }

    int e = beg;
    for (; e + 1 < end; e += 2) {
        int s0 = g_csr[e], s1 = g_csr[e + 1];
        float n0 = di * g_dinv[s0], n1 = di * g_dinv[s1];
        const float4* r0 = (const float4*)(tmp + (size_t)s0 * d);
        const float4* r1 = (const float4*)(tmp + (size_t)s1 * d);
#pragma unroll
        for (int j = 0; j < 2; j++) {
            int c = tid + j * 128;
            if (c < nc4) {
                float4 v0 = r0[c], v1 = r1[c];
                acc0[j].x += v0.x * n0; acc0[j].y += v0.y * n0;
                acc0[j].z += v0.z * n0; acc0[j].w += v0.w * n0;
                acc1[j].x += v1.x * n1; acc1[j].y += v1.y * n1;
                acc1[j].z += v1.z * n1; acc1[j].w += v1.w * n1;
            }
        }
    }
    if (e < end) {
        int s0 = g_csr[e];
        float n0 = di * g_dinv[s0];
        const float4* r0 = (const float4*)(tmp + (size_t)s0 * d);
#pragma unroll
        for (int j = 0; j < 2; j++) {
            int c = tid + j * 128;
            if (c < nc4) {
                float4 v0 = r0[c];
                acc0[j].x += v0.x * n0; acc0[j].y += v0.y * n0;
                acc0[j].z += v0.z * n0; acc0[j].w += v0.w * n0;
            }
        }
    }

    const float4* b4 = (const float4*)bias;
#pragma unroll
    for (int j = 0; j < 2; j++) {
        int c = tid + j * 128;
        if (c >= nc4) continue;
        float4 bv = b4[c];
        float4 r = make_float4(to_tf32(fmaxf(acc0[j].x + acc1[j].x + bv.x, 0.f)),
                               to_tf32(fmaxf(acc0[j].y + acc1[j].y + bv.y, 0.f)),
                               to_tf32(fmaxf(acc0[j].z + acc1[j].z + bv.z, 0.f)),
                               to_tf32(fmaxf(acc0[j].w + acc1[j].w + bv.w, 0.f)));
        ((float4*)(o + (size_t)node * d))[c] = r;
    }
}

// ---------------- CSR aggregation, narrow (d = 128 or 256), warp per node --------
__global__ void __launch_bounds__(128)
agg_narrow_kernel(const float* __restrict__ tmp, const float* __restrict__ bias,
                  float* __restrict__ outf, float* __restrict__ o, int d, int last)
{
    int node = blockIdx.x * 4 + (threadIdx.x >> 5);
    if (node >= N_NODES) return;
    int lane = threadIdx.x & 31;
    int nc4 = d >> 2;   // 32 or 64
    float di = g_dinv[node];
    int beg = g_rowptr[node];
    int end = g_rowptr[node + 1];

    float4 acc[2];
    float selfn = di * di;
    const float4* selfrow = (const float4*)(tmp + (size_t)node * d);
#pragma unroll
    for (int j = 0; j < 2; j++) {
        int c = lane + j * 32;
        if (c < nc4) {
            float4 v = selfrow[c];
            acc[j] = make_float4(v.x * selfn, v.y * selfn, v.z * selfn, v.w * selfn);
        } else acc[j] = make_float4(0.f, 0.f, 0.f, 0.f);
    }

    for (int e = beg; e < end; e++) {
        int src = g_csr[e];
        float nrm = di * g_dinv[src];
        const float4* row = (const float4*)(tmp + (size_t)src * d);
#pragma unroll
        for (int j = 0; j < 2; j++) {
            int c = lane + j * 32;
            if (c < nc4) {
                float4 v = row[c];
                acc[j].x += v.x * nrm; acc[j].y += v.y * nrm;
                acc[j].z += v.z * nrm; acc[j].w += v.w * nrm;
            }
        }
    }

    const float4* b4 = (const float4*)bias;
#pragma unroll
    for (int j = 0; j < 2; j++) {
        int c = lane + j * 32;
        if (c >= nc4) continue;
        float4 bv = b4[c];
        float4 r = make_float4(acc[j].x + bv.x, acc[j].y + bv.y,
                               acc[j].z + bv.z, acc[j].w + bv.w);
        if (last) {
            ((float4*)(outf + (size_t)node * d))[c] = r;
        } else {
            r = make_float4(to_tf32(fmaxf(r.x, 0.f)), to_tf32(fmaxf(r.y, 0.f)),
                            to_tf32(fmaxf(r.z, 0.f)), to_tf32(fmaxf(r.w, 0.f)));
            ((float4*)(o + (size_t)node * d))[c] = r;
        }
    }
}

// ---------------- launch ----------------
extern "C" void kernel_launch(void* const* d_in, const int* in_sizes, int n_in,
                              void* d_out, int out_size) {
    const float* x = (const float*)d_in[0];
    const void*  e = d_in[1];
    const float* W[5] = {(const float*)d_in[2], (const float*)d_in[4],
                         (const float*)d_in[6], (const float*)d_in[8],
                         (const float*)d_in[10]};
    const float* b[5] = {(const float*)d_in[3], (const float*)d_in[5],
                         (const float*)d_in[7], (const float*)d_in[9],
                         (const float*)d_in[11]};
    float* out = (float*)d_out;

    float *bufA, *bufB, *w, *tm;
    cudaGetSymbolAddress((void**)&bufA, g_A);
    cudaGetSymbolAddress((void**)&bufB, g_B);
    cudaGetSymbolAddress((void**)&w, g_W);
    cudaGetSymbolAddress((void**)&tm, g_tmp);

    static int attr_set = 0;
    if (!attr_set) {
        cudaFuncSetAttribute(bgemm_kernel, cudaFuncAttributeMaxDynamicSharedMemorySize, 65536);
        attr_set = 1;
    }

    // graph preprocessing
    zero_deg_kernel<<<(N_NODES + 255) / 256, 256>>>(e);
    count_deg_kernel<<<(N_EDGES + 255) / 256, 256>>>(e);
    block_sum_kernel<<<GSCAN, 1024>>>();
    scan_partials_kernel<<<1, 1>>>();
    scatter_scan_kernel<<<GSCAN, 1024>>>();
    fill_csr_kernel<<<(N_EDGES + 255) / 256, 256>>>(e);

    const int dims[6] = {512, 2048, 1024, 512, 256, 128};
    long long woff[5];
    {
        long long o = 0;
        for (int l = 0; l < 5; l++) { woff[l] = o; o += (long long)dims[l] * dims[l + 1]; }
    }
    for (int l = 0; l < 5; l++) {
        int cnt = dims[l] * dims[l + 1];
        convert_w_kernel<<<(cnt + 255) / 256, 256>>>(W[l], woff[l], dims[l], dims[l + 1]);
    }

    int gy = (N_NODES + 127) / 128;

    // L1: aggregate x first (d=512, linearity), then GEMM with fused
    //     bias+relu+tf32 epilogue straight into buffer B (2048-wide).
    aggx_kernel<<<N_NODES, 128>>>(x, bufA);
    {
        dim3 grid(2048 / 128, gy);
        bgemm_kernel<<<grid, 256, 65536>>>(bufA, w + woff[0], nullptr, b[0], bufB,
                                           N_NODES, 2048, 512, 1);
    }

    // L2..L5: GEMM -> tmp fp32 -> aggregate (+bias, +relu/tf32 or final fp32)
    float* in4[4] = {bufB, bufA, bufB, bufA};
    float* ot4[4] = {bufA, bufB, bufA, nullptr};
    for (int l = 1; l < 5; l++) {
        int K = dims[l], N = dims[l + 1];
        dim3 grid(N / 128, gy);
        bgemm_kernel<<<grid, 256, 65536>>>(in4[l - 1], w + woff[l], tm, nullptr, nullptr,
                                           N_NODES, N, K, 0);
        if (N >= 512) {
            agg_wide_kernel<<<N_NODES, 128>>>(tm, b[l], ot4[l - 1], N);
        } else {
            agg_narrow_kernel<<<(N_NODES + 3) / 4, 128>>>(tm, b[l], out, ot4[l - 1],
                                                          N, l == 4 ? 1 : 0);
        }
    }
}

// round 16
// speedup vs baseline: 1.5006x; 1.5006x over previous
#include <cuda_runtime.h>
#include <cuda_bf16.h>
#include <cstdint>

#define N_NODES 50000
#define N_EDGES 320000
#define GSCAN   ((N_NODES + 1023) / 1024)

// ---------------- static scratch (no allocations allowed) ----------------
__device__ float g_A[(size_t)N_NODES * 1024];   // activation buffer A (tf32-rounded fp32)
__device__ float g_B[(size_t)N_NODES * 2048];   // activation buffer B (tf32-rounded fp32)
__device__ float g_tmp[(size_t)N_NODES * 1024]; // GEMM fp32 out (pre-agg), max d=1024
__device__ float g_W[4 * 1024 * 1024];          // transposed weights (tf32-rounded fp32)

__device__ int   g_deg[N_NODES];
__device__ float g_dinv[N_NODES];
__device__ int   g_rowptr[N_NODES + 1];
__device__ int   g_fill[N_NODES];
__device__ int   g_csr[N_EDGES];
__device__ int   g_bsum[64];
__device__ int   g_is64;

// ---------------- tf32 rounding helper ----------------
__device__ __forceinline__ float to_tf32(float v) {
    uint32_t u;
    asm("cvt.rna.tf32.f32 %0, %1;" : "=r"(u) : "f"(v));
    return __uint_as_float(u);
}

// ---------------- index dtype handling ----------------
__device__ __forceinline__ int get_idx(const void* e, long long i) {
    if (g_is64) return (int)((const long long*)e)[i];
    return ((const int*)e)[i];
}

// ---------------- graph preprocessing ----------------
// also detects index dtype (block 0, thread 0) — consumed by LATER kernels only
__global__ void zero_deg_kernel(const void* e) {
    int i = blockIdx.x * blockDim.x + threadIdx.x;
    if (i < N_NODES) g_deg[i] = 0;
    if (blockIdx.x == 0 && threadIdx.x == 0) {
        const int* w = (const int*)e;
        int all0 = 1;
        for (int j = 1; j < 64; j += 2)
            if (w[j] != 0) all0 = 0;
        g_is64 = all0;
    }
}

__global__ void count_deg_kernel(const void* e) {
    int i = blockIdx.x * blockDim.x + threadIdx.x;
    if (i >= N_EDGES) return;
    int dst = get_idx(e, (long long)N_EDGES + i);
    atomicAdd(&g_deg[dst], 1);
}

__global__ void block_sum_kernel() {
    int i = blockIdx.x * 1024 + threadIdx.x;
    int v = (i < N_NODES) ? g_deg[i] : 0;
    int lane = threadIdx.x & 31, warp = threadIdx.x >> 5;
#pragma unroll
    for (int off = 16; off > 0; off >>= 1) v += __shfl_down_sync(0xffffffffu, v, off);
    __shared__ int ws[32];
    if (lane == 0) ws[warp] = v;
    __syncthreads();
    if (warp == 0) {
        int s = ws[lane];
#pragma unroll
        for (int off = 16; off > 0; off >>= 1) s += __shfl_down_sync(0xffffffffu, s, off);
        if (lane == 0) g_bsum[blockIdx.x] = s;
    }
}

__global__ void scan_partials_kernel() {
    int acc = 0;
    for (int i = 0; i < GSCAN; i++) { int t = g_bsum[i]; g_bsum[i] = acc; acc += t; }
    g_rowptr[N_NODES] = acc;
}

__global__ void scatter_scan_kernel() {
    int i = blockIdx.x * 1024 + threadIdx.x;
    int v = (i < N_NODES) ? g_deg[i] : 0;
    int lane = threadIdx.x & 31, warp = threadIdx.x >> 5;
    int incl = v;
#pragma unroll
    for (int off = 1; off < 32; off <<= 1) {
        int t = __shfl_up_sync(0xffffffffu, incl, off);
        if (lane >= off) incl += t;
    }
    __shared__ int ws[32];
    if (lane == 31) ws[warp] = incl;
    __syncthreads();
    if (warp == 0) {
        int s = ws[lane];
#pragma unroll
        for (int off = 1; off < 32; off <<= 1) {
            int t = __shfl_up_sync(0xffffffffu, s, off);
            if (lane >= off) s += t;
        }
        ws[lane] = s;
    }
    __syncthreads();
    int wbase = (warp == 0) ? 0 : ws[warp - 1];
    int excl = g_bsum[blockIdx.x] + wbase + incl - v;
    if (i < N_NODES) {
        g_rowptr[i] = excl;
        g_fill[i]   = excl;
        g_dinv[i]   = rsqrtf((float)v + 1.0f);
    }
}

__global__ void fill_csr_kernel(const void* e) {
    int i = blockIdx.x * blockDim.x + threadIdx.x;
    if (i >= N_EDGES) return;
    int src = get_idx(e, i);
    int dst = get_idx(e, (long long)N_EDGES + i);
    int pos = atomicAdd(&g_fill[dst], 1);
    g_csr[pos] = src;
}

// ---------------- weight conversion: all 5 layers in ONE launch ----------------
// W_l [K,N] row-major -> g_W at woff_l as [N,K] tf32.
// Layer offsets are compile-time constants.
struct WPtrs { const float* p[5]; };

__global__ void convert_w_all_kernel(WPtrs wp) {
    const int KD[5] = {512, 2048, 1024, 512, 256};
    const int ND[5] = {2048, 1024, 512, 256, 128};
    const int CNT[5] = {512 * 2048, 2048 * 1024, 1024 * 512, 512 * 256, 256 * 128};
    const int OFF[5] = {0, 512 * 2048, 512 * 2048 + 2048 * 1024,
                        512 * 2048 + 2048 * 1024 + 1024 * 512,
                        512 * 2048 + 2048 * 1024 + 1024 * 512 + 512 * 256};
    int idx = blockIdx.x * blockDim.x + threadIdx.x;
    int l = 0;
#pragma unroll
    for (int i = 1; i < 5; i++)
        if (idx >= OFF[i]) l = i;
    int local = idx - OFF[l];
    if (local >= CNT[l]) return;
    int N = ND[l], K = KD[l];
    int k = local / N, n = local % N;
    g_W[OFF[l] + (size_t)n * K + k] = to_tf32(wp.p[l][local]);
}

// ---------------- tf32 tensor-core GEMM (mma.sync.m16n8k8) — R14 exact ----------------
// C[M,N] = A[M,K] @ Wt[N,K]^T, operands tf32-rounded fp32.
// 128x128x32 tiles, 256 threads (8 warps of 64x32), cp.async 2-stage,
// 128B rows with 8-chunk xor swizzle, ldmatrix.x4 (b16 view == tf32 frag).
// mode 0: store fp32 C.  mode 1: fused bias+relu+tf32-round into O.
__device__ __forceinline__ void ldm4(uint32_t* r, uint32_t addr) {
    asm volatile("ldmatrix.sync.aligned.m8n8.x4.shared.b16 {%0,%1,%2,%3}, [%4];"
                 : "=r"(r[0]), "=r"(r[1]), "=r"(r[2]), "=r"(r[3]) : "r"(addr));
}

__device__ __forceinline__ void mma_tf32(float* c, const uint32_t* a, const uint32_t* b) {
    asm volatile(
        "mma.sync.aligned.m16n8k8.row.col.f32.tf32.tf32.f32 "
        "{%0,%1,%2,%3},{%4,%5,%6,%7},{%8,%9},{%0,%1,%2,%3};"
        : "+f"(c[0]), "+f"(c[1]), "+f"(c[2]), "+f"(c[3])
        : "r"(a[0]), "r"(a[1]), "r"(a[2]), "r"(a[3]), "r"(b[0]), "r"(b[1]));
}

__device__ __forceinline__ void cp16(uint32_t dst, const void* src, bool pred) {
    int sz = pred ? 16 : 0;
    asm volatile("cp.async.cg.shared.global [%0], [%1], 16, %2;\n"
                 :: "r"(dst), "l"(src), "r"(sz));
}

// stage (32KB): A rows[0,16K): 128 x 128B; B rows[16K,32K): 128 x 128B.
// row r: 8 chunks of 16B (4 tf32); logical chunk c at physical c ^ (r & 7).
__device__ __forceinline__ void load_stage(
    uint32_t sbase, int stage,
    const float* __restrict__ A, const float* __restrict__ B,
    int bm, int bn, int k0, int M, int K, int tid)
{
    uint32_t st = sbase + stage * 32768;
#pragma unroll
    for (int h = 0; h < 4; h++) {
        int i = tid + h * 256;
        int row = i >> 3, c = i & 7;
        uint32_t doff = (uint32_t)(row * 128 + (c ^ (row & 7)) * 16);
        long arow = bm + row;
        bool av = arow < M;
        long ar = av ? arow : 0;
        cp16(st + doff, A + (size_t)ar * K + k0 + c * 4, av);
    }
#pragma unroll
    for (int h = 0; h < 4; h++) {
        int i = tid + h * 256;
        int row = i >> 3, c = i & 7;
        uint32_t doff = (uint32_t)(row * 128 + (c ^ (row & 7)) * 16);
        cp16(st + 16384 + doff, B + (size_t)(bn + row) * K + k0 + c * 4, true);
    }
    asm volatile("cp.async.commit_group;\n");
}

__global__ void __launch_bounds__(256)
bgemm_kernel(const float* __restrict__ A, const float* __restrict__ W,
             float* __restrict__ C, const float* __restrict__ bias,
             float* __restrict__ O, int M, int N, int K, int mode)
{
    extern __shared__ __align__(16) char smem[];
    uint32_t sbase = (uint32_t)__cvta_generic_to_shared(smem);

    int tid  = threadIdx.x;
    int lane = tid & 31, wid = tid >> 5;
    int wm = (wid >> 2) * 64;
    int wn = (wid & 3) * 32;
    int bm = blockIdx.y * 128;
    int bn = blockIdx.x * 128;

    float acc[4][4][4];
#pragma unroll
    for (int i = 0; i < 4; i++)
#pragma unroll
        for (int j = 0; j < 4; j++)
#pragma unroll
            for (int r = 0; r < 4; r++) acc[i][j][r] = 0.f;

    int nk = K >> 5;
    load_stage(sbase, 0, A, W, bm, bn, 0, M, K, tid);

    int lr = lane & 15, lc = lane >> 4;

    for (int kt = 0; kt < nk; kt++) {
        if (kt + 1 < nk) {
            load_stage(sbase, (kt + 1) & 1, A, W, bm, bn, (kt + 1) * 32, M, K, tid);
            asm volatile("cp.async.wait_group 1;\n");
        } else {
            asm volatile("cp.async.wait_group 0;\n");
        }
        __syncthreads();

        uint32_t st = sbase + (kt & 1) * 32768;
#pragma unroll
        for (int s = 0; s < 4; s++) {          // 4 k8-steps per 32-k tile
            int c = s * 2 + lc;                // logical 16B chunk
            uint32_t bf[4][2];
#pragma unroll
            for (int p = 0; p < 2; p++) {
                int row = wn + p * 16 + lr;
                uint32_t r4[4];
                ldm4(r4, st + 16384 + (uint32_t)(row * 128 + ((c ^ (row & 7)) << 4)));
                bf[2 * p][0] = r4[0];     bf[2 * p][1] = r4[2];
                bf[2 * p + 1][0] = r4[1]; bf[2 * p + 1][1] = r4[3];
            }
#pragma unroll
            for (int fm = 0; fm < 4; fm++) {
                int row = wm + fm * 16 + lr;
                uint32_t a4[4];
                ldm4(a4, st + (uint32_t)(row * 128 + ((c ^ (row & 7)) << 4)));
#pragma unroll
                for (int fn = 0; fn < 4; fn++)
                    mma_tf32(acc[fm][fn], a4, bf[fn]);
            }
        }
        __syncthreads();
    }

    int g = lane >> 2, tg = lane & 3;
    if (mode == 0) {
#pragma unroll
        for (int fm = 0; fm < 4; fm++) {
#pragma unroll
            for (int fn = 0; fn < 4; fn++) {
                int row = bm + wm + fm * 16 + g;
                int col = bn + wn + fn * 8 + tg * 2;
                if (row < M)
                    *(float2*)&C[(size_t)row * N + col] = make_float2(acc[fm][fn][0], acc[fm][fn][1]);
                if (row + 8 < M)
                    *(float2*)&C[(size_t)(row + 8) * N + col] = make_float2(acc[fm][fn][2], acc[fm][fn][3]);
            }
        }
    } else {
#pragma unroll
        for (int fm = 0; fm < 4; fm++) {
#pragma unroll
            for (int fn = 0; fn < 4; fn++) {
                int col = bn + wn + fn * 8 + tg * 2;
                float2 bv = *(const float2*)&bias[col];
#pragma unroll
                for (int h = 0; h < 2; h++) {
                    int row = bm + wm + fm * 16 + g + h * 8;
                    if (row >= M) continue;
                    float v0 = to_tf32(fmaxf(acc[fm][fn][h * 2]     + bv.x, 0.f));
                    float v1 = to_tf32(fmaxf(acc[fm][fn][h * 2 + 1] + bv.y, 0.f));
                    *(float2*)&O[(size_t)row * N + col] = make_float2(v0, v1);
                }
            }
        }
    }
}

// ---------------- aggregation of raw input x (d=512) -> tf32 fp32 ----------------
__global__ void __launch_bounds__(128)
aggx_kernel(const float* __restrict__ x, float* __restrict__ o)
{
    const int d = 512;
    int node = blockIdx.x;
    int tid  = threadIdx.x;
    float di = g_dinv[node];
    int beg = g_rowptr[node];
    int end = g_rowptr[node + 1];

    float selfn = di * di;
    float4 v = ((const float4*)(x + (size_t)node * d))[tid];
    float4 acc = make_float4(v.x * selfn, v.y * selfn, v.z * selfn, v.w * selfn);

    for (int e = beg; e < end; e++) {
        int src = g_csr[e];
        float nrm = di * g_dinv[src];
        float4 w = ((const float4*)(x + (size_t)src * d))[tid];
        acc.x += w.x * nrm; acc.y += w.y * nrm;
        acc.z += w.z * nrm; acc.w += w.w * nrm;
    }

    float4 r = make_float4(to_tf32(acc.x), to_tf32(acc.y), to_tf32(acc.z), to_tf32(acc.w));
    ((float4*)(o + (size_t)node * d))[tid] = r;
}

// ---------------- CSR aggregation, wide (d = 512 or 1024), block per node --------
__global__ void __launch_bounds__(128)
agg_wide_kernel(const float* __restrict__ tmp, const float* __restrict__ bias,
                float* __restrict__ o, int d)
{
    int node = blockIdx.x;
    int tid  = threadIdx.x;
    float di = g_dinv[node];
    int beg = g_rowptr[node];
    int end = g_rowptr[node + 1];
    int nc4 = d >> 2;

    float4 acc[2];
    float selfn = di * di;
    const float4* selfrow = (const float4*)(tmp + (size_t)node * d);
#pragma unroll
    for (int j = 0; j < 2; j++) {
        int c = tid + j * 128;
        if (c < nc4) {
            float4 v = selfrow[c];
            acc[j] = make_float4(v.x * selfn, v.y * selfn, v.z * selfn, v.w * selfn);
        } else acc[j] = make_float4(0.f, 0.f, 0.f, 0.f);
    }

    for (int e = beg; e < end; e++) {
        int src = g_csr[e];
        float nrm = di * g_dinv[src];
        const float4* row = (const float4*)(tmp + (size_t)src * d);
#pragma unroll
        for (int j = 0; j < 2; j++) {
            int c = tid + j * 128;
            if (c < nc4) {
                float4 v = row[c];
                acc[j].x += v.x * nrm; acc[j].y += v.y * nrm;
                acc[j].z += v.z * nrm; acc[j].w += v.w * nrm;
            }
        }
    }

    const float4* b4 = (const float4*)bias;
#pragma unroll
    for (int j = 0; j < 2; j++) {
        int c = tid + j * 128;
        if (c >= nc4) continue;
        float4 bv = b4[c];
        float4 r = make_float4(to_tf32(fmaxf(acc[j].x + bv.x, 0.f)),
                               to_tf32(fmaxf(acc[j].y + bv.y, 0.f)),
                               to_tf32(fmaxf(acc[j].z + bv.z, 0.f)),
                               to_tf32(fmaxf(acc[j].w + bv.w, 0.f)));
        ((float4*)(o + (size_t)node * d))[c] = r;
    }
}

// ---------------- CSR aggregation, narrow (d = 128 or 256), warp per node --------
__global__ void __launch_bounds__(128)
agg_narrow_kernel(const float* __restrict__ tmp, const float* __restrict__ bias,
                  float* __restrict__ outf, float* __restrict__ o, int d, int last)
{
    int node = blockIdx.x * 4 + (threadIdx.x >> 5);
    if (node >= N_NODES) return;
    int lane = threadIdx.x & 31;
    int nc4 = d >> 2;   // 32 or 64
    float di = g_dinv[node];
    int beg = g_rowptr[node];
    int end = g_rowptr[node + 1];

    float4 acc[2];
    float selfn = di * di;
    const float4* selfrow = (const float4*)(tmp + (size_t)node * d);
#pragma unroll
    for (int j = 0; j < 2; j++) {
        int c = lane + j * 32;
        if (c < nc4) {
            float4 v = selfrow[c];
            acc[j] = make_float4(v.x * selfn, v.y * selfn, v.z * selfn, v.w * selfn);
        } else acc[j] = make_float4(0.f, 0.f, 0.f, 0.f);
    }

    for (int e = beg; e < end; e++) {
        int src = g_csr[e];
        float nrm = di * g_dinv[src];
        const float4* row = (const float4*)(tmp + (size_t)src * d);
#pragma unroll
        for (int j = 0; j < 2; j++) {
            int c = lane + j * 32;
            if (c < nc4) {
                float4 v = row[c];
                acc[j].x += v.x * nrm; acc[j].y += v.y * nrm;
                acc[j].z += v.z * nrm; acc[j].w += v.w * nrm;
            }
        }
    }

    const float4* b4 = (const float4*)bias;
#pragma unroll
    for (int j = 0; j < 2; j++) {
        int c = lane + j * 32;
        if (c >= nc4) continue;
        float4 bv = b4[c];
        float4 r = make_float4(acc[j].x + bv.x, acc[j].y + bv.y,
                               acc[j].z + bv.z, acc[j].w + bv.w);
        if (last) {
            ((float4*)(outf + (size_t)node * d))[c] = r;
        } else {
            r = make_float4(to_tf32(fmaxf(r.x, 0.f)), to_tf32(fmaxf(r.y, 0.f)),
                            to_tf32(fmaxf(r.z, 0.f)), to_tf32(fmaxf(r.w, 0.f)));
            ((float4*)(o + (size_t)node * d))[c] = r;
        }
    }
}

// ---------------- launch ----------------
extern "C" void kernel_launch(void* const* d_in, const int* in_sizes, int n_in,
                              void* d_out, int out_size) {
    const float* x = (const float*)d_in[0];
    const void*  e = d_in[1];
    const float* W[5] = {(const float*)d_in[2], (const float*)d_in[4],
                         (const float*)d_in[6], (const float*)d_in[8],
                         (const float*)d_in[10]};
    const float* b[5] = {(const float*)d_in[3], (const float*)d_in[5],
                         (const float*)d_in[7], (const float*)d_in[9],
                         (const float*)d_in[11]};
    float* out = (float*)d_out;

    float *bufA, *bufB, *w, *tm;
    cudaGetSymbolAddress((void**)&bufA, g_A);
    cudaGetSymbolAddress((void**)&bufB, g_B);
    cudaGetSymbolAddress((void**)&w, g_W);
    cudaGetSymbolAddress((void**)&tm, g_tmp);

    static int attr_set = 0;
    if (!attr_set) {
        cudaFuncSetAttribute(bgemm_kernel, cudaFuncAttributeMaxDynamicSharedMemorySize, 65536);
        attr_set = 1;
    }

    // graph preprocessing (detect folded into zero_deg)
    zero_deg_kernel<<<(N_NODES + 255) / 256, 256>>>(e);
    count_deg_kernel<<<(N_EDGES + 255) / 256, 256>>>(e);
    block_sum_kernel<<<GSCAN, 1024>>>();
    scan_partials_kernel<<<1, 1>>>();
    scatter_scan_kernel<<<GSCAN, 1024>>>();
    fill_csr_kernel<<<(N_EDGES + 255) / 256, 256>>>(e);

    const int dims[6] = {512, 2048, 1024, 512, 256, 128};
    long long woff[5];
    {
        long long o = 0;
        for (int l = 0; l < 5; l++) { woff[l] = o; o += (long long)dims[l] * dims[l + 1]; }
    }

    // single fused weight-conversion launch (3.75M elements)
    {
        WPtrs wp;
        for (int l = 0; l < 5; l++) wp.p[l] = W[l];
        int total = 512 * 2048 + 2048 * 1024 + 1024 * 512 + 512 * 256 + 256 * 128;
        convert_w_all_kernel<<<(total + 255) / 256, 256>>>(wp);
    }

    int gy = (N_NODES + 127) / 128;

    // L1: aggregate x first (d=512, linearity), then GEMM with fused
    //     bias+relu+tf32 epilogue straight into buffer B (2048-wide).
    aggx_kernel<<<N_NODES, 128>>>(x, bufA);
    {
        dim3 grid(2048 / 128, gy);
        bgemm_kernel<<<grid, 256, 65536>>>(bufA, w + woff[0], nullptr, b[0], bufB,
                                           N_NODES, 2048, 512, 1);
    }

    // L2..L5: GEMM -> tmp fp32 -> aggregate (+bias, +relu/tf32 or final fp32)
    float* in4[4] = {bufB, bufA, bufB, bufA};
    float* ot4[4] = {bufA, bufB, bufA, nullptr};
    for (int l = 1; l < 5; l++) {
        int K = dims[l], N = dims[l + 1];
        dim3 grid(N / 128, gy);
        bgemm_kernel<<<grid, 256, 65536>>>(in4[l - 1], w + woff[l], tm, nullptr, nullptr,
                                           N_NODES, N, K, 0);
        if (N >= 512) {
            agg_wide_kernel<<<N_NODES, 128>>>(tm, b[l], ot4[l - 1], N);
        } else {
            agg_narrow_kernel<<<(N_NODES + 3) / 4, 128>>>(tm, b[l], out, ot4[l - 1],
                                                          N, l == 4 ? 1 : 0);
        }
    }
}